// round 1
// baseline (speedup 1.0000x reference)
#include <cuda_runtime.h>
#include <cstddef>

// Problem constants
// B=16, N=512, T=24, F=64, BT=B*T=384
#define T_DIM 24
#define N_DIM 512
#define F_DIM 64
#define BT_DIM 384

// Scratch (device globals: allocation-free per harness rules)
static __device__ float g_EE[N_DIM * N_DIM];                       // 1 MB, emb @ emb^T
static __device__ float g_S[(size_t)BT_DIM * N_DIM * N_DIM];       // 403 MB, logits -> P (in-place)
static __device__ float g_VW[(size_t)BT_DIM * N_DIM * 128];        // 100 MB, [XW | UW] per batch

// ---------------------------------------------------------------------------
// k_ee: EE = emb @ emb^T  (512x512, K=64). 64x64 tile per block, 256 threads.
// ---------------------------------------------------------------------------
__global__ void k_ee(const float* __restrict__ emb) {
    __shared__ float As[64][68];   // row-major (r, k)
    __shared__ float Bs[64][65];   // k-major   (k, c)
    const int rb = blockIdx.y * 64, cb = blockIdx.x * 64;
    const int tid = threadIdx.x;

    #pragma unroll
    for (int it = 0; it < 4; ++it) {
        int i = tid + it * 256;
        int r = i >> 4, k4 = i & 15;
        float4 a = *(const float4*)(emb + (rb + r) * 64 + k4 * 4);
        *(float4*)(&As[r][k4 * 4]) = a;
        float4 w = *(const float4*)(emb + (cb + r) * 64 + k4 * 4);
        Bs[k4 * 4 + 0][r] = w.x; Bs[k4 * 4 + 1][r] = w.y;
        Bs[k4 * 4 + 2][r] = w.z; Bs[k4 * 4 + 3][r] = w.w;
    }
    __syncthreads();

    const int ty = tid >> 4, tx = tid & 15;
    float acc[4][4] = {};
    #pragma unroll 8
    for (int k = 0; k < 64; ++k) {
        float a[4], b[4];
        #pragma unroll
        for (int i = 0; i < 4; ++i) a[i] = As[ty * 4 + i][k];
        #pragma unroll
        for (int j = 0; j < 4; ++j) b[j] = Bs[k][tx + 16 * j];
        #pragma unroll
        for (int i = 0; i < 4; ++i)
            #pragma unroll
            for (int j = 0; j < 4; ++j) acc[i][j] = fmaf(a[i], b[j], acc[i][j]);
    }
    #pragma unroll
    for (int i = 0; i < 4; ++i)
        #pragma unroll
        for (int j = 0; j < 4; ++j)
            g_EE[(rb + ty * 4 + i) * N_DIM + cb + tx + 16 * j] = acc[i][j];
}

// ---------------------------------------------------------------------------
// k_vw: XW = X @ W1^T, UW = U @ W1^T for each bt. 32 rows x 64 outs per block.
// X[bt][n][f] = ori[b*786432 + n*1536 + t*64 + f],  bt = b*24 + t
// ---------------------------------------------------------------------------
__global__ void k_vw(const float* __restrict__ ori, const float* __restrict__ unc,
                     const float* __restrict__ W1) {
    __shared__ float Xs[32][68], Us[32][68];  // row-major (r, k)
    __shared__ float Ws[64][65];              // k-major   (f, o)
    const int rb = blockIdx.x * 32;
    const int bt = blockIdx.y;
    const int b = bt / T_DIM, t = bt % T_DIM;
    const int tid = threadIdx.x;
    const size_t base = (size_t)b * 786432 + (size_t)t * 64;

    #pragma unroll
    for (int it = 0; it < 2; ++it) {
        int i = tid + it * 256;
        int r = i >> 4, k4 = i & 15;
        size_t g = base + (size_t)(rb + r) * 1536 + k4 * 4;
        *(float4*)(&Xs[r][k4 * 4]) = *(const float4*)(ori + g);
        *(float4*)(&Us[r][k4 * 4]) = *(const float4*)(unc + g);
    }
    #pragma unroll
    for (int it = 0; it < 4; ++it) {
        int i = tid + it * 256;
        int o = i >> 4, f4 = i & 15;
        float4 w = *(const float4*)(W1 + o * 64 + f4 * 4);
        Ws[f4 * 4 + 0][o] = w.x; Ws[f4 * 4 + 1][o] = w.y;
        Ws[f4 * 4 + 2][o] = w.z; Ws[f4 * 4 + 3][o] = w.w;
    }
    __syncthreads();

    const int ty = tid >> 4, tx = tid & 15;
    float ax[2][4] = {}, au[2][4] = {};
    #pragma unroll 8
    for (int k = 0; k < 64; ++k) {
        float xa[2], ua[2], w[4];
        #pragma unroll
        for (int i = 0; i < 2; ++i) { xa[i] = Xs[ty * 2 + i][k]; ua[i] = Us[ty * 2 + i][k]; }
        #pragma unroll
        for (int j = 0; j < 4; ++j) w[j] = Ws[k][tx + 16 * j];
        #pragma unroll
        for (int i = 0; i < 2; ++i)
            #pragma unroll
            for (int j = 0; j < 4; ++j) {
                ax[i][j] = fmaf(xa[i], w[j], ax[i][j]);
                au[i][j] = fmaf(ua[i], w[j], au[i][j]);
            }
    }
    #pragma unroll
    for (int i = 0; i < 2; ++i) {
        size_t row = ((size_t)bt * N_DIM + rb + ty * 2 + i) * 128;
        #pragma unroll
        for (int j = 0; j < 4; ++j) {
            g_VW[row + tx + 16 * j]      = ax[i][j];
            g_VW[row + 64 + tx + 16 * j] = au[i][j];
        }
    }
}

// ---------------------------------------------------------------------------
// k_logits: S = relu(X @ X^T + EE) per batch. 64x128 tile, K=64 single pass.
// dyn smem: As[64][68] + Bs[64][129]
// ---------------------------------------------------------------------------
__global__ void k_logits(const float* __restrict__ ori) {
    extern __shared__ float sm[];
    float (*As)[68]  = (float(*)[68])sm;                 // (r, k)
    float (*Bs)[129] = (float(*)[129])(sm + 64 * 68);    // (k, c)
    const int cb = blockIdx.x * 128, rb = blockIdx.y * 64, bt = blockIdx.z;
    const int b = bt / T_DIM, t = bt % T_DIM;
    const int tid = threadIdx.x;
    const size_t base = (size_t)b * 786432 + (size_t)t * 64;

    #pragma unroll
    for (int it = 0; it < 4; ++it) {
        int i = tid + it * 256;
        int r = i >> 4, k4 = i & 15;
        *(float4*)(&As[r][k4 * 4]) =
            *(const float4*)(ori + base + (size_t)(rb + r) * 1536 + k4 * 4);
    }
    #pragma unroll
    for (int it = 0; it < 8; ++it) {
        int i = tid + it * 256;
        int c = i >> 4, k4 = i & 15;
        float4 v = *(const float4*)(ori + base + (size_t)(cb + c) * 1536 + k4 * 4);
        Bs[k4 * 4 + 0][c] = v.x; Bs[k4 * 4 + 1][c] = v.y;
        Bs[k4 * 4 + 2][c] = v.z; Bs[k4 * 4 + 3][c] = v.w;
    }
    __syncthreads();

    const int ty = tid >> 4, tx = tid & 15;
    float acc[4][8] = {};
    #pragma unroll 4
    for (int k = 0; k < 64; ++k) {
        float a[4], bv[8];
        #pragma unroll
        for (int i = 0; i < 4; ++i) a[i] = As[ty * 4 + i][k];
        #pragma unroll
        for (int j = 0; j < 8; ++j) bv[j] = Bs[k][tx + 16 * j];
        #pragma unroll
        for (int i = 0; i < 4; ++i)
            #pragma unroll
            for (int j = 0; j < 8; ++j) acc[i][j] = fmaf(a[i], bv[j], acc[i][j]);
    }

    #pragma unroll
    for (int i = 0; i < 4; ++i) {
        int r = rb + ty * 4 + i;
        size_t srow = ((size_t)bt * N_DIM + r) * N_DIM;
        #pragma unroll
        for (int j = 0; j < 8; ++j) {
            int c = cb + tx + 16 * j;
            float v = acc[i][j] + g_EE[r * N_DIM + c];
            g_S[srow + c] = fmaxf(v, 0.0f);
        }
    }
}

// ---------------------------------------------------------------------------
// k_softmax: in-place row softmax over g_S. One row per block, 128 threads.
// ---------------------------------------------------------------------------
__global__ void k_softmax() {
    const size_t row = ((size_t)blockIdx.y * N_DIM + blockIdx.x) * N_DIM;
    float4* p = (float4*)(g_S + row);
    const int tid = threadIdx.x;
    float4 v = p[tid];

    float m = fmaxf(fmaxf(v.x, v.y), fmaxf(v.z, v.w));
    #pragma unroll
    for (int o = 16; o > 0; o >>= 1) m = fmaxf(m, __shfl_xor_sync(0xffffffffu, m, o));
    __shared__ float smax[4];
    int w = tid >> 5, l = tid & 31;
    if (l == 0) smax[w] = m;
    __syncthreads();
    m = fmaxf(fmaxf(smax[0], smax[1]), fmaxf(smax[2], smax[3]));

    float4 e;
    e.x = __expf(v.x - m); e.y = __expf(v.y - m);
    e.z = __expf(v.z - m); e.w = __expf(v.w - m);
    float s = e.x + e.y + e.z + e.w;
    #pragma unroll
    for (int o = 16; o > 0; o >>= 1) s += __shfl_xor_sync(0xffffffffu, s, o);
    __shared__ float ssum[4];
    if (l == 0) ssum[w] = s;
    __syncthreads();
    s = ssum[0] + ssum[1] + ssum[2] + ssum[3];

    float inv = 1.0f / s;
    e.x *= inv; e.y *= inv; e.z *= inv; e.w *= inv;
    p[tid] = e;
}

// ---------------------------------------------------------------------------
// k_out: OUT = relu(P @ [XW|UW]) + scatter to (B,N,T,F) layout for of / uf.
// 64 rows x 128 cols per block, K=512 in 8 chunks. dyn smem Ps[64][68]+Vs[64][128]
// ---------------------------------------------------------------------------
__global__ void k_out(float* __restrict__ out, size_t uf_off) {
    extern __shared__ float sm[];
    float (*Ps)[68]  = (float(*)[68])sm;               // (r, k)
    float (*Vs)[128] = (float(*)[128])(sm + 64 * 68);  // (k, c)
    const int rb = blockIdx.x * 64, bt = blockIdx.y;
    const int b = bt / T_DIM, t = bt % T_DIM;
    const int tid = threadIdx.x;
    const int ty = tid >> 4, tx = tid & 15;

    float acc[4][8] = {};
    for (int kt = 0; kt < 8; ++kt) {
        #pragma unroll
        for (int it = 0; it < 4; ++it) {
            int i = tid + it * 256;
            int r = i >> 4, k4 = i & 15;
            *(float4*)(&Ps[r][k4 * 4]) =
                *(const float4*)(g_S + ((size_t)bt * N_DIM + rb + r) * N_DIM + kt * 64 + k4 * 4);
        }
        #pragma unroll
        for (int it = 0; it < 8; ++it) {
            int i = tid + it * 256;
            int k = i >> 5, c4 = i & 31;
            *(float4*)(&Vs[k][c4 * 4]) =
                *(const float4*)(g_VW + ((size_t)bt * N_DIM + kt * 64 + k) * 128 + c4 * 4);
        }
        __syncthreads();

        #pragma unroll 4
        for (int k = 0; k < 64; ++k) {
            float pv[4], vv[8];
            #pragma unroll
            for (int i = 0; i < 4; ++i) pv[i] = Ps[ty * 4 + i][k];
            #pragma unroll
            for (int j = 0; j < 8; ++j) vv[j] = Vs[k][tx + 16 * j];
            #pragma unroll
            for (int i = 0; i < 4; ++i)
                #pragma unroll
                for (int j = 0; j < 8; ++j) acc[i][j] = fmaf(pv[i], vv[j], acc[i][j]);
        }
        __syncthreads();
    }

    #pragma unroll
    for (int i = 0; i < 4; ++i) {
        int n = rb + ty * 4 + i;
        size_t obase = (size_t)b * 786432 + (size_t)n * 1536 + (size_t)t * 64;
        #pragma unroll
        for (int j = 0; j < 8; ++j) {
            int c = tx + 16 * j;
            float v = fmaxf(acc[i][j], 0.0f);
            if (c < 64) out[obase + c] = v;
            else        out[uf_off + obase + (c - 64)] = v;
        }
    }
}

// ---------------------------------------------------------------------------
extern "C" void kernel_launch(void* const* d_in, const int* in_sizes, int n_in,
                              void* d_out, int out_size) {
    const float* ori = (const float*)d_in[0];   // (16,512,24,64)
    const float* unc = (const float*)d_in[1];   // (16,512,24,64)
    const float* emb = (const float*)d_in[2];   // (512,64)
    const float* W1  = (const float*)d_in[3];   // (64,64)
    float* out = (float*)d_out;                 // [of | uf]
    const size_t uf_off = (size_t)out_size / 2;

    const int SMEM_LOGITS = (64 * 68 + 64 * 129) * 4;  // 50432 B
    const int SMEM_OUT    = (64 * 68 + 64 * 128) * 4;  // 50176 B
    cudaFuncSetAttribute(k_logits, cudaFuncAttributeMaxDynamicSharedMemorySize, SMEM_LOGITS);
    cudaFuncSetAttribute(k_out,    cudaFuncAttributeMaxDynamicSharedMemorySize, SMEM_OUT);

    k_ee<<<dim3(8, 8), 256>>>(emb);
    k_vw<<<dim3(16, BT_DIM), 256>>>(ori, unc, W1);
    k_logits<<<dim3(4, 8, BT_DIM), 256, SMEM_LOGITS>>>(ori);
    k_softmax<<<dim3(N_DIM, BT_DIM), 128>>>();
    k_out<<<dim3(8, BT_DIM), 256, SMEM_OUT>>>(out, uf_off);
}

// round 2
// speedup vs baseline: 1.2275x; 1.2275x over previous
#include <cuda_runtime.h>
#include <cstddef>

// B=16, N=512, T=24, F=64, BT=384
#define T_DIM 24
#define N_DIM 512
#define BT_DIM 384

// Scratch (device globals: allocation-free per harness rules)
static __device__ float g_EE[N_DIM * N_DIM];                       // 1 MB
static __device__ float g_S[(size_t)BT_DIM * N_DIM * N_DIM];       // 403 MB (relu'd logits)
static __device__ float g_VW[(size_t)BT_DIM * N_DIM * 128];        // 100 MB [XW|UW]
static __device__ float g_M[(size_t)BT_DIM * N_DIM];               // row max
static __device__ float g_IS[(size_t)BT_DIM * N_DIM];              // row 1/sum

typedef unsigned long long u64;
__device__ __forceinline__ u64 pack2(float lo, float hi) {
    u64 r; asm("mov.b64 %0, {%1, %2};" : "=l"(r) : "f"(lo), "f"(hi)); return r;
}
__device__ __forceinline__ u64 ffma2(u64 a, u64 b, u64 c) {
    u64 d; asm("fma.rn.f32x2 %0, %1, %2, %3;" : "=l"(d) : "l"(a), "l"(b), "l"(c)); return d;
}
__device__ __forceinline__ float2 unpack2(u64 v) {
    float2 r; asm("mov.b64 {%0, %1}, %2;" : "=f"(r.x), "=f"(r.y) : "l"(v)); return r;
}

#define AP 68    // (r,k) pitch: 16B-aligned float4 stores
#define BP 130   // (k,c) pitch: 8B-aligned LDS.64 reads (even)
#define VP 132   // (k,c) pitch: 16B-aligned float4 stores + 8B LDS.64

// ---------------------------------------------------------------------------
// k_ee: EE = emb @ emb^T  (512x512, K=64)
// ---------------------------------------------------------------------------
__global__ void k_ee(const float* __restrict__ emb) {
    __shared__ float As[64][68];
    __shared__ float Bs[64][65];
    const int rb = blockIdx.y * 64, cb = blockIdx.x * 64;
    const int tid = threadIdx.x;
    #pragma unroll
    for (int it = 0; it < 4; ++it) {
        int i = tid + it * 256;
        int r = i >> 4, k4 = i & 15;
        float4 a = *(const float4*)(emb + (rb + r) * 64 + k4 * 4);
        *(float4*)(&As[r][k4 * 4]) = a;
        float4 w = *(const float4*)(emb + (cb + r) * 64 + k4 * 4);
        Bs[k4 * 4 + 0][r] = w.x; Bs[k4 * 4 + 1][r] = w.y;
        Bs[k4 * 4 + 2][r] = w.z; Bs[k4 * 4 + 3][r] = w.w;
    }
    __syncthreads();
    const int ty = tid >> 4, tx = tid & 15;
    float acc[4][4] = {};
    #pragma unroll 8
    for (int k = 0; k < 64; ++k) {
        float a[4], b[4];
        #pragma unroll
        for (int i = 0; i < 4; ++i) a[i] = As[ty * 4 + i][k];
        #pragma unroll
        for (int j = 0; j < 4; ++j) b[j] = Bs[k][tx + 16 * j];
        #pragma unroll
        for (int i = 0; i < 4; ++i)
            #pragma unroll
            for (int j = 0; j < 4; ++j) acc[i][j] = fmaf(a[i], b[j], acc[i][j]);
    }
    #pragma unroll
    for (int i = 0; i < 4; ++i)
        #pragma unroll
        for (int j = 0; j < 4; ++j)
            g_EE[(rb + ty * 4 + i) * N_DIM + cb + tx + 16 * j] = acc[i][j];
}

// ---------------------------------------------------------------------------
// k_vw: VW[bt][n] = [ X@W1^T | U@W1^T ]
// ---------------------------------------------------------------------------
__global__ void k_vw(const float* __restrict__ ori, const float* __restrict__ unc,
                     const float* __restrict__ W1) {
    __shared__ float Xs[32][68], Us[32][68];
    __shared__ float Ws[64][65];
    const int rb = blockIdx.x * 32;
    const int bt = blockIdx.y;
    const int b = bt / T_DIM, t = bt % T_DIM;
    const int tid = threadIdx.x;
    const size_t base = (size_t)b * 786432 + (size_t)t * 64;
    #pragma unroll
    for (int it = 0; it < 2; ++it) {
        int i = tid + it * 256;
        int r = i >> 4, k4 = i & 15;
        size_t g = base + (size_t)(rb + r) * 1536 + k4 * 4;
        *(float4*)(&Xs[r][k4 * 4]) = *(const float4*)(ori + g);
        *(float4*)(&Us[r][k4 * 4]) = *(const float4*)(unc + g);
    }
    #pragma unroll
    for (int it = 0; it < 4; ++it) {
        int i = tid + it * 256;
        int o = i >> 4, f4 = i & 15;
        float4 w = *(const float4*)(W1 + o * 64 + f4 * 4);
        Ws[f4 * 4 + 0][o] = w.x; Ws[f4 * 4 + 1][o] = w.y;
        Ws[f4 * 4 + 2][o] = w.z; Ws[f4 * 4 + 3][o] = w.w;
    }
    __syncthreads();
    const int ty = tid >> 4, tx = tid & 15;
    float ax[2][4] = {}, au[2][4] = {};
    #pragma unroll 8
    for (int k = 0; k < 64; ++k) {
        float xa[2], ua[2], w[4];
        #pragma unroll
        for (int i = 0; i < 2; ++i) { xa[i] = Xs[ty * 2 + i][k]; ua[i] = Us[ty * 2 + i][k]; }
        #pragma unroll
        for (int j = 0; j < 4; ++j) w[j] = Ws[k][tx + 16 * j];
        #pragma unroll
        for (int i = 0; i < 2; ++i)
            #pragma unroll
            for (int j = 0; j < 4; ++j) {
                ax[i][j] = fmaf(xa[i], w[j], ax[i][j]);
                au[i][j] = fmaf(ua[i], w[j], au[i][j]);
            }
    }
    #pragma unroll
    for (int i = 0; i < 2; ++i) {
        size_t row = ((size_t)bt * N_DIM + rb + ty * 2 + i) * 128;
        #pragma unroll
        for (int j = 0; j < 4; ++j) {
            g_VW[row + tx + 16 * j]      = ax[i][j];
            g_VW[row + 64 + tx + 16 * j] = au[i][j];
        }
    }
}

// ---------------------------------------------------------------------------
// k_logits: S = relu(X @ X^T + EE). 128x128 tile, f32x2 FMA, K=64 one pass.
// ---------------------------------------------------------------------------
__global__ __launch_bounds__(256, 2) void k_logits(const float* __restrict__ ori) {
    extern __shared__ float sm[];
    float (*As)[AP] = (float(*)[AP])sm;                // (r, k) 128x68
    float (*Bs)[BP] = (float(*)[BP])(sm + 128 * AP);   // (k, c) 64x130
    const int cb = blockIdx.x * 128, rb = blockIdx.y * 128, bt = blockIdx.z;
    const int b = bt / T_DIM, t = bt % T_DIM;
    const int tid = threadIdx.x;
    const size_t base = (size_t)b * 786432 + (size_t)t * 64;

    #pragma unroll
    for (int it = 0; it < 8; ++it) {
        int i = tid + it * 256;
        int r = i >> 4, q = i & 15;
        *(float4*)(&As[r][q * 4]) =
            *(const float4*)(ori + base + (size_t)(rb + r) * 1536 + q * 4);
    }
    #pragma unroll
    for (int it = 0; it < 8; ++it) {
        int i = tid + it * 256;
        int c = i >> 4, q = i & 15;
        float4 v = *(const float4*)(ori + base + (size_t)(cb + c) * 1536 + q * 4);
        Bs[q * 4 + 0][c] = v.x; Bs[q * 4 + 1][c] = v.y;
        Bs[q * 4 + 2][c] = v.z; Bs[q * 4 + 3][c] = v.w;
    }
    __syncthreads();

    const int ty = tid >> 4, tx = tid & 15;
    u64 acc[8][4] = {};
    #pragma unroll 8
    for (int k = 0; k < 64; ++k) {
        u64 bp[4];
        #pragma unroll
        for (int j = 0; j < 4; ++j) bp[j] = *(const u64*)(&Bs[k][2 * tx + 32 * j]);
        #pragma unroll
        for (int i = 0; i < 8; ++i) {
            float a = As[ty + 16 * i][k];
            u64 ad = pack2(a, a);
            #pragma unroll
            for (int j = 0; j < 4; ++j) acc[i][j] = ffma2(ad, bp[j], acc[i][j]);
        }
    }

    #pragma unroll
    for (int i = 0; i < 8; ++i) {
        int r = rb + ty + 16 * i;
        size_t srow = ((size_t)bt * N_DIM + r) * N_DIM;
        #pragma unroll
        for (int j = 0; j < 4; ++j) {
            int c = cb + 2 * tx + 32 * j;
            float2 e = *(const float2*)(g_EE + (size_t)r * N_DIM + c);
            float2 v = unpack2(acc[i][j]);
            float2 o;
            o.x = fmaxf(v.x + e.x, 0.0f);
            o.y = fmaxf(v.y + e.y, 0.0f);
            *(float2*)(g_S + srow + c) = o;
        }
    }
}

// ---------------------------------------------------------------------------
// k_stats: per-row max + 1/sum(exp(v-max)) of g_S. No S write-back.
// ---------------------------------------------------------------------------
__global__ void k_stats() {
    const size_t row = (size_t)blockIdx.y * N_DIM + blockIdx.x;
    const float4* p = (const float4*)(g_S + row * N_DIM);
    const int tid = threadIdx.x;
    float4 v = p[tid];

    float m = fmaxf(fmaxf(v.x, v.y), fmaxf(v.z, v.w));
    #pragma unroll
    for (int o = 16; o > 0; o >>= 1) m = fmaxf(m, __shfl_xor_sync(0xffffffffu, m, o));
    __shared__ float smax[4], ssum[4];
    int w = tid >> 5, l = tid & 31;
    if (l == 0) smax[w] = m;
    __syncthreads();
    m = fmaxf(fmaxf(smax[0], smax[1]), fmaxf(smax[2], smax[3]));

    float s = __expf(v.x - m) + __expf(v.y - m) + __expf(v.z - m) + __expf(v.w - m);
    #pragma unroll
    for (int o = 16; o > 0; o >>= 1) s += __shfl_xor_sync(0xffffffffu, s, o);
    if (l == 0) ssum[w] = s;
    __syncthreads();
    if (tid == 0) {
        g_M[row] = m;
        g_IS[row] = 1.0f / (ssum[0] + ssum[1] + ssum[2] + ssum[3]);
    }
}

// ---------------------------------------------------------------------------
// k_out: OUT = relu(softmax(S) @ [XW|UW]); exp-normalize fused into Ps load.
// 128 rows x 128 cols per block, K=512 in 8 chunks, f32x2 FMA.
// ---------------------------------------------------------------------------
__global__ __launch_bounds__(256, 2) void k_out(float* __restrict__ out, size_t uf_off) {
    extern __shared__ float sm[];
    float (*Ps)[AP] = (float(*)[AP])sm;                    // (r, k) 128x68
    float (*Vs)[VP] = (float(*)[VP])(sm + 128 * AP);       // (k, c) 64x132
    float* Ms = sm + 128 * AP + 64 * VP;                   // 128 row maxima
    float* IS = Ms + 128;                                  // 128 row inv-sums
    const int rb = blockIdx.x * 128, bt = blockIdx.y;
    const int b = bt / T_DIM, t = bt % T_DIM;
    const int tid = threadIdx.x;

    if (tid < 128) {
        Ms[tid] = g_M[(size_t)bt * N_DIM + rb + tid];
        IS[tid] = g_IS[(size_t)bt * N_DIM + rb + tid];
    }
    __syncthreads();

    const int ty = tid >> 4, tx = tid & 15;
    u64 acc[8][4] = {};
    for (int kt = 0; kt < 8; ++kt) {
        #pragma unroll
        for (int it = 0; it < 8; ++it) {
            int i = tid + it * 256;
            int r = i >> 4, q = i & 15;
            float4 v = *(const float4*)(g_S +
                ((size_t)bt * N_DIM + rb + r) * N_DIM + kt * 64 + q * 4);
            float mr = Ms[r], isr = IS[r];
            float4 pv;
            pv.x = __expf(v.x - mr) * isr;
            pv.y = __expf(v.y - mr) * isr;
            pv.z = __expf(v.z - mr) * isr;
            pv.w = __expf(v.w - mr) * isr;
            *(float4*)(&Ps[r][q * 4]) = pv;
        }
        #pragma unroll
        for (int it = 0; it < 8; ++it) {
            int i = tid + it * 256;
            int k = i >> 5, q = i & 31;
            *(float4*)(&Vs[k][q * 4]) =
                *(const float4*)(g_VW + ((size_t)bt * N_DIM + kt * 64 + k) * 128 + q * 4);
        }
        __syncthreads();

        #pragma unroll 8
        for (int k = 0; k < 64; ++k) {
            u64 bp[4];
            #pragma unroll
            for (int j = 0; j < 4; ++j) bp[j] = *(const u64*)(&Vs[k][2 * tx + 32 * j]);
            #pragma unroll
            for (int i = 0; i < 8; ++i) {
                float a = Ps[ty + 16 * i][k];
                u64 ad = pack2(a, a);
                #pragma unroll
                for (int j = 0; j < 4; ++j) acc[i][j] = ffma2(ad, bp[j], acc[i][j]);
            }
        }
        __syncthreads();
    }

    #pragma unroll
    for (int i = 0; i < 8; ++i) {
        int n = rb + ty + 16 * i;
        size_t obase = (size_t)b * 786432 + (size_t)n * 1536 + (size_t)t * 64;
        #pragma unroll
        for (int j = 0; j < 4; ++j) {
            int c = 2 * tx + 32 * j;
            float2 v = unpack2(acc[i][j]);
            v.x = fmaxf(v.x, 0.0f);
            v.y = fmaxf(v.y, 0.0f);
            if (c < 64) *(float2*)(out + obase + c) = v;
            else        *(float2*)(out + uf_off + obase + (c - 64)) = v;
        }
    }
}

// ---------------------------------------------------------------------------
extern "C" void kernel_launch(void* const* d_in, const int* in_sizes, int n_in,
                              void* d_out, int out_size) {
    const float* ori = (const float*)d_in[0];   // (16,512,24,64)
    const float* unc = (const float*)d_in[1];   // (16,512,24,64)
    const float* emb = (const float*)d_in[2];   // (512,64)
    const float* W1  = (const float*)d_in[3];   // (64,64)
    float* out = (float*)d_out;                 // [of | uf]
    const size_t uf_off = (size_t)out_size / 2;

    const int SMEM_LOGITS = (128 * AP + 64 * BP) * 4;        // 68096 B
    const int SMEM_OUT    = (128 * AP + 64 * VP + 256) * 4;  // 69632 B
    cudaFuncSetAttribute(k_logits, cudaFuncAttributeMaxDynamicSharedMemorySize, SMEM_LOGITS);
    cudaFuncSetAttribute(k_out,    cudaFuncAttributeMaxDynamicSharedMemorySize, SMEM_OUT);

    k_ee<<<dim3(8, 8), 256>>>(emb);
    k_vw<<<dim3(16, BT_DIM), 256>>>(ori, unc, W1);
    k_logits<<<dim3(4, 4, BT_DIM), 256, SMEM_LOGITS>>>(ori);
    k_stats<<<dim3(N_DIM, BT_DIM), 128>>>();
    k_out<<<dim3(4, BT_DIM), 256, SMEM_OUT>>>(out, uf_off);
}

// round 4
// speedup vs baseline: 1.2960x; 1.0558x over previous
#include <cuda_runtime.h>
#include <cstddef>

// B=16, N=512, T=24, F=64, BT=384
#define T_DIM 24
#define N_DIM 512
#define BT_DIM 384

// Scratch (device globals: allocation-free per harness rules)
static __device__ float g_EE[N_DIM * N_DIM];                       // 1 MB
static __device__ float g_S[(size_t)BT_DIM * N_DIM * N_DIM];       // 403 MB: exp(relu(s)-D)
static __device__ float g_VW[(size_t)BT_DIM * N_DIM * 128];        // 100 MB [XW|UW]
static __device__ float g_D[(size_t)BT_DIM * N_DIM];               // diag shift per row
static __device__ float g_RSP[(size_t)BT_DIM * 4 * N_DIM];         // row-sum partials (4 col blocks)

typedef unsigned long long u64;
__device__ __forceinline__ u64 pack2(float lo, float hi) {
    u64 r; asm("mov.b64 %0, {%1, %2};" : "=l"(r) : "f"(lo), "f"(hi)); return r;
}
__device__ __forceinline__ u64 ffma2(u64 a, u64 b, u64 c) {
    u64 d; asm("fma.rn.f32x2 %0, %1, %2, %3;" : "=l"(d) : "l"(a), "l"(b), "l"(c)); return d;
}
__device__ __forceinline__ float2 unpack2(u64 v) {
    float2 r; asm("mov.b64 {%0, %1}, %2;" : "=f"(r.x), "=f"(r.y) : "l"(v)); return r;
}

#define AP 68    // (r,k) pitch
#define BP 130   // (k,c) pitch, even for LDS.64
#define VP 132   // (k,c) pitch, 16B-aligned stores + LDS.64

// ---------------------------------------------------------------------------
// k_ee: EE = emb @ emb^T  (512x512, K=64)
// ---------------------------------------------------------------------------
__global__ void k_ee(const float* __restrict__ emb) {
    __shared__ float As[64][68];
    __shared__ float Bs[64][65];
    const int rb = blockIdx.y * 64, cb = blockIdx.x * 64;
    const int tid = threadIdx.x;
    #pragma unroll
    for (int it = 0; it < 4; ++it) {
        int i = tid + it * 256;
        int r = i >> 4, k4 = i & 15;
        float4 a = *(const float4*)(emb + (rb + r) * 64 + k4 * 4);
        *(float4*)(&As[r][k4 * 4]) = a;
        float4 w = *(const float4*)(emb + (cb + r) * 64 + k4 * 4);
        Bs[k4 * 4 + 0][r] = w.x; Bs[k4 * 4 + 1][r] = w.y;
        Bs[k4 * 4 + 2][r] = w.z; Bs[k4 * 4 + 3][r] = w.w;
    }
    __syncthreads();
    const int ty = tid >> 4, tx = tid & 15;
    float acc[4][4] = {};
    #pragma unroll 8
    for (int k = 0; k < 64; ++k) {
        float a[4], b[4];
        #pragma unroll
        for (int i = 0; i < 4; ++i) a[i] = As[ty * 4 + i][k];
        #pragma unroll
        for (int j = 0; j < 4; ++j) b[j] = Bs[k][tx + 16 * j];
        #pragma unroll
        for (int i = 0; i < 4; ++i)
            #pragma unroll
            for (int j = 0; j < 4; ++j) acc[i][j] = fmaf(a[i], b[j], acc[i][j]);
    }
    #pragma unroll
    for (int i = 0; i < 4; ++i)
        #pragma unroll
        for (int j = 0; j < 4; ++j)
            g_EE[(rb + ty * 4 + i) * N_DIM + cb + tx + 16 * j] = acc[i][j];
}

// ---------------------------------------------------------------------------
// k_diag: D[bt][n] = ||x_btn||^2 + EE[n][n]. 16 rows per block, 16 lanes/row.
// ---------------------------------------------------------------------------
__global__ void k_diag(const float* __restrict__ ori) {
    const int bt = blockIdx.y;
    const int b = bt / T_DIM, t = bt % T_DIM;
    const int tid = threadIdx.x;
    const int rloc = tid >> 4, q = tid & 15;
    const int n = blockIdx.x * 16 + rloc;
    const size_t g = (size_t)b * 786432 + (size_t)n * 1536 + (size_t)t * 64 + q * 4;
    float4 v = *(const float4*)(ori + g);
    float s = v.x * v.x + v.y * v.y + v.z * v.z + v.w * v.w;
    #pragma unroll
    for (int o = 8; o > 0; o >>= 1) s += __shfl_xor_sync(0xffffffffu, s, o);
    if (q == 0)
        g_D[(size_t)bt * N_DIM + n] = s + g_EE[(size_t)n * N_DIM + n];
}

// ---------------------------------------------------------------------------
// k_vw: VW[bt][n] = [ X@W1^T | U@W1^T ]
// ---------------------------------------------------------------------------
__global__ void k_vw(const float* __restrict__ ori, const float* __restrict__ unc,
                     const float* __restrict__ W1) {
    __shared__ float Xs[32][68], Us[32][68];
    __shared__ float Ws[64][65];
    const int rb = blockIdx.x * 32;
    const int bt = blockIdx.y;
    const int b = bt / T_DIM, t = bt % T_DIM;
    const int tid = threadIdx.x;
    const size_t base = (size_t)b * 786432 + (size_t)t * 64;
    #pragma unroll
    for (int it = 0; it < 2; ++it) {
        int i = tid + it * 256;
        int r = i >> 4, k4 = i & 15;
        size_t g = base + (size_t)(rb + r) * 1536 + k4 * 4;
        *(float4*)(&Xs[r][k4 * 4]) = *(const float4*)(ori + g);
        *(float4*)(&Us[r][k4 * 4]) = *(const float4*)(unc + g);
    }
    #pragma unroll
    for (int it = 0; it < 4; ++it) {
        int i = tid + it * 256;
        int o = i >> 4, f4 = i & 15;
        float4 w = *(const float4*)(W1 + o * 64 + f4 * 4);
        Ws[f4 * 4 + 0][o] = w.x; Ws[f4 * 4 + 1][o] = w.y;
        Ws[f4 * 4 + 2][o] = w.z; Ws[f4 * 4 + 3][o] = w.w;
    }
    __syncthreads();
    const int ty = tid >> 4, tx = tid & 15;
    float ax[2][4] = {}, au[2][4] = {};
    #pragma unroll 8
    for (int k = 0; k < 64; ++k) {
        float xa[2], ua[2], w[4];
        #pragma unroll
        for (int i = 0; i < 2; ++i) { xa[i] = Xs[ty * 2 + i][k]; ua[i] = Us[ty * 2 + i][k]; }
        #pragma unroll
        for (int j = 0; j < 4; ++j) w[j] = Ws[k][tx + 16 * j];
        #pragma unroll
        for (int i = 0; i < 2; ++i)
            #pragma unroll
            for (int j = 0; j < 4; ++j) {
                ax[i][j] = fmaf(xa[i], w[j], ax[i][j]);
                au[i][j] = fmaf(ua[i], w[j], au[i][j]);
            }
    }
    #pragma unroll
    for (int i = 0; i < 2; ++i) {
        size_t row = ((size_t)bt * N_DIM + rb + ty * 2 + i) * 128;
        #pragma unroll
        for (int j = 0; j < 4; ++j) {
            g_VW[row + tx + 16 * j]      = ax[i][j];
            g_VW[row + 64 + tx + 16 * j] = au[i][j];
        }
    }
}

// ---------------------------------------------------------------------------
// k_logits: E = exp(relu(X@X^T + EE) - D). Store E + deterministic row-sum
// partials per column block. 128x128 tile, f32x2 FMA, K=64 one pass.
// ---------------------------------------------------------------------------
__global__ __launch_bounds__(256, 2) void k_logits(const float* __restrict__ ori) {
    extern __shared__ float sm[];
    float (*As)[AP] = (float(*)[AP])sm;                // (r, k) 128x68
    float (*Bs)[BP] = (float(*)[BP])(sm + 128 * AP);   // (k, c) 64x130
    const int bx = blockIdx.x;
    const int cb = bx * 128, rb = blockIdx.y * 128, bt = blockIdx.z;
    const int b = bt / T_DIM, t = bt % T_DIM;
    const int tid = threadIdx.x;
    const size_t base = (size_t)b * 786432 + (size_t)t * 64;

    #pragma unroll
    for (int it = 0; it < 8; ++it) {
        int i = tid + it * 256;
        int r = i >> 4, q = i & 15;
        *(float4*)(&As[r][q * 4]) =
            *(const float4*)(ori + base + (size_t)(rb + r) * 1536 + q * 4);
    }
    #pragma unroll
    for (int it = 0; it < 8; ++it) {
        int i = tid + it * 256;
        int c = i >> 4, q = i & 15;
        float4 v = *(const float4*)(ori + base + (size_t)(cb + c) * 1536 + q * 4);
        Bs[q * 4 + 0][c] = v.x; Bs[q * 4 + 1][c] = v.y;
        Bs[q * 4 + 2][c] = v.z; Bs[q * 4 + 3][c] = v.w;
    }
    __syncthreads();

    const int ty = tid >> 4, tx = tid & 15;
    u64 acc[8][4] = {};
    #pragma unroll 8
    for (int k = 0; k < 64; ++k) {
        u64 bp[4];
        #pragma unroll
        for (int j = 0; j < 4; ++j) bp[j] = *(const u64*)(&Bs[k][2 * tx + 32 * j]);
        #pragma unroll
        for (int i = 0; i < 8; ++i) {
            float a = As[ty + 16 * i][k];
            u64 ad = pack2(a, a);
            #pragma unroll
            for (int j = 0; j < 4; ++j) acc[i][j] = ffma2(ad, bp[j], acc[i][j]);
        }
    }

    // Epilogue: exp(relu(s+ee) - D[r]), store E, deterministic partial sums.
    #pragma unroll
    for (int i = 0; i < 8; ++i) {
        int r = rb + ty + 16 * i;
        float dr = g_D[(size_t)bt * N_DIM + r];
        size_t srow = ((size_t)bt * N_DIM + r) * N_DIM;
        float rsum = 0.0f;
        #pragma unroll
        for (int j = 0; j < 4; ++j) {
            int c = cb + 2 * tx + 32 * j;
            float2 e = *(const float2*)(g_EE + (size_t)r * N_DIM + c);
            float2 v = unpack2(acc[i][j]);
            float2 o;
            o.x = __expf(fmaxf(v.x + e.x, 0.0f) - dr);
            o.y = __expf(fmaxf(v.y + e.y, 0.0f) - dr);
            *(float2*)(g_S + srow + c) = o;
            rsum += o.x + o.y;
        }
        #pragma unroll
        for (int o = 8; o > 0; o >>= 1)
            rsum += __shfl_xor_sync(0xffffffffu, rsum, o);
        if (tx == 0)
            g_RSP[((size_t)bt * 4 + bx) * N_DIM + r] = rsum;
    }
}

// ---------------------------------------------------------------------------
// k_out: OUT = relu( (1/rowsum) * (E @ [XW|UW]) ). Pure GEMM, scalar epilogue.
// 128 rows x 128 cols per block, K=512 in 8 chunks, f32x2 FMA.
// ---------------------------------------------------------------------------
__global__ __launch_bounds__(256, 2) void k_out(float* __restrict__ out, size_t uf_off) {
    extern __shared__ float sm[];
    float (*Ps)[AP] = (float(*)[AP])sm;                 // (r, k) 128x68
    float (*Vs)[VP] = (float(*)[VP])(sm + 128 * AP);    // (k, c) 64x132
    const int rb = blockIdx.x * 128, bt = blockIdx.y;
    const int b = bt / T_DIM, t = bt % T_DIM;
    const int tid = threadIdx.x;
    const int ty = tid >> 4, tx = tid & 15;

    u64 acc[8][4] = {};
    for (int kt = 0; kt < 8; ++kt) {
        #pragma unroll
        for (int it = 0; it < 8; ++it) {
            int i = tid + it * 256;
            int r = i >> 4, q = i & 15;
            *(float4*)(&Ps[r][q * 4]) = *(const float4*)(g_S +
                ((size_t)bt * N_DIM + rb + r) * N_DIM + kt * 64 + q * 4);
        }
        #pragma unroll
        for (int it = 0; it < 8; ++it) {
            int i = tid + it * 256;
            int k = i >> 5, q = i & 31;
            *(float4*)(&Vs[k][q * 4]) =
                *(const float4*)(g_VW + ((size_t)bt * N_DIM + kt * 64 + k) * 128 + q * 4);
        }
        __syncthreads();

        #pragma unroll 8
        for (int k = 0; k < 64; ++k) {
            u64 bp[4];
            #pragma unroll
            for (int j = 0; j < 4; ++j) bp[j] = *(const u64*)(&Vs[k][2 * tx + 32 * j]);
            #pragma unroll
            for (int i = 0; i < 8; ++i) {
                float a = Ps[ty + 16 * i][k];
                u64 ad = pack2(a, a);
                #pragma unroll
                for (int j = 0; j < 4; ++j) acc[i][j] = ffma2(ad, bp[j], acc[i][j]);
            }
        }
        __syncthreads();
    }

    #pragma unroll
    for (int i = 0; i < 8; ++i) {
        int n = rb + ty + 16 * i;
        size_t rsb = (size_t)bt * 4 * N_DIM + n;
        float rs = g_RSP[rsb] + g_RSP[rsb + N_DIM] +
                   g_RSP[rsb + 2 * N_DIM] + g_RSP[rsb + 3 * N_DIM];
        float inv = 1.0f / rs;
        size_t obase = (size_t)b * 786432 + (size_t)n * 1536 + (size_t)t * 64;
        #pragma unroll
        for (int j = 0; j < 4; ++j) {
            int c = 2 * tx + 32 * j;
            float2 v = unpack2(acc[i][j]);
            v.x = fmaxf(v.x * inv, 0.0f);
            v.y = fmaxf(v.y * inv, 0.0f);
            if (c < 64) *(float2*)(out + obase + c) = v;
            else        *(float2*)(out + uf_off + obase + (c - 64)) = v;
        }
    }
}

// ---------------------------------------------------------------------------
extern "C" void kernel_launch(void* const* d_in, const int* in_sizes, int n_in,
                              void* d_out, int out_size) {
    const float* ori = (const float*)d_in[0];   // (16,512,24,64)
    const float* unc = (const float*)d_in[1];   // (16,512,24,64)
    const float* emb = (const float*)d_in[2];   // (512,64)
    const float* W1  = (const float*)d_in[3];   // (64,64)
    float* out = (float*)d_out;                 // [of | uf]
    const size_t uf_off = (size_t)out_size / 2;

    const int SMEM_LOGITS = (128 * AP + 64 * BP) * 4;   // 68096 B
    const int SMEM_OUT    = (128 * AP + 64 * VP) * 4;   // 68608 B
    cudaFuncSetAttribute(k_logits, cudaFuncAttributeMaxDynamicSharedMemorySize, SMEM_LOGITS);
    cudaFuncSetAttribute(k_out,    cudaFuncAttributeMaxDynamicSharedMemorySize, SMEM_OUT);

    k_ee<<<dim3(8, 8), 256>>>(emb);
    k_diag<<<dim3(32, BT_DIM), 256>>>(ori);
    k_vw<<<dim3(16, BT_DIM), 256>>>(ori, unc, W1);
    k_logits<<<dim3(4, 4, BT_DIM), 256, SMEM_LOGITS>>>(ori);
    k_out<<<dim3(4, BT_DIM), 256, SMEM_OUT>>>(out, uf_off);
}